// round 14
// baseline (speedup 1.0000x reference)
#include <cuda_runtime.h>

#define NATOMS  1024
#define NBATCH  32
#define TPB     256
#define JQ      4              // j-quarters
#define JTILE   256            // atoms per j-quarter
#define NQUADS  64             // quads per j-quarter
// grid = 32 * 4 * 4 = 512 blocks of 256 threads

typedef unsigned long long ull;

__device__ __forceinline__ ull f2pack(float lo, float hi) {
    ull r;
    asm("mov.b64 %0, {%1, %2};" : "=l"(r)
        : "r"(__float_as_uint(lo)), "r"(__float_as_uint(hi)));
    return r;
}
__device__ __forceinline__ void f2unpack(ull v, float& lo, float& hi) {
    unsigned a, b;
    asm("mov.b64 {%0, %1}, %2;" : "=r"(a), "=r"(b) : "l"(v));
    lo = __uint_as_float(a);
    hi = __uint_as_float(b);
}
__device__ __forceinline__ ull f2add(ull a, ull b) {
    ull r; asm("add.rn.f32x2 %0, %1, %2;" : "=l"(r) : "l"(a), "l"(b)); return r;
}
__device__ __forceinline__ ull f2mul(ull a, ull b) {
    ull r; asm("mul.rn.f32x2 %0, %1, %2;" : "=l"(r) : "l"(a), "l"(b)); return r;
}
__device__ __forceinline__ ull f2fma(ull a, ull b, ull c) {
    ull r; asm("fma.rn.f32x2 %0, %1, %2, %3;" : "=l"(r) : "l"(a), "l"(b), "l"(c)); return r;
}

// Pre-pass: 4 blocks per batch; mean + oscillator init (quarter-0 writes out[b]).
__global__ __launch_bounds__(256) void lj_pre(const float* __restrict__ pos,
                                              float* __restrict__ out) {
    __shared__ float wr[8 * 3];
    __shared__ float er[8];
    __shared__ float smean[3];

    const int blk = blockIdx.x;
    const int b   = blk >> 2;
    const int q   = blk & 3;
    const int tid = threadIdx.x;
    const int lane = tid & 31, warp = tid >> 5;
    const float* __restrict__ p = pos + (size_t)b * NATOMS * 3;

    float ax[4], ay[4], az[4];
    float mx = 0.0f, my = 0.0f, mz = 0.0f;
    #pragma unroll
    for (int k = 0; k < 4; k++) {
        const int a = tid + 256 * k;
        ax[k] = p[3 * a + 0]; ay[k] = p[3 * a + 1]; az[k] = p[3 * a + 2];
        mx += ax[k]; my += ay[k]; mz += az[k];
    }
    #pragma unroll
    for (int o = 16; o > 0; o >>= 1) {
        mx += __shfl_xor_sync(0xFFFFFFFFu, mx, o);
        my += __shfl_xor_sync(0xFFFFFFFFu, my, o);
        mz += __shfl_xor_sync(0xFFFFFFFFu, mz, o);
    }
    if (lane == 0) { wr[warp * 3] = mx; wr[warp * 3 + 1] = my; wr[warp * 3 + 2] = mz; }
    __syncthreads();
    if (tid == 0) {
        float sx = 0.0f, sy = 0.0f, sz = 0.0f;
        #pragma unroll
        for (int k = 0; k < 8; k++) { sx += wr[k*3]; sy += wr[k*3+1]; sz += wr[k*3+2]; }
        const float inv_n = 1.0f / (float)NATOMS;
        smean[0] = sx * inv_n; smean[1] = sy * inv_n; smean[2] = sz * inv_n;
    }
    __syncthreads();
    const float cmx = smean[0], cmy = smean[1], cmz = smean[2];

    float e = 0.0f;
    float* __restrict__ f = out + NBATCH + (size_t)b * NATOMS * 3;
    #pragma unroll
    for (int k = 0; k < 4; k++) {
        float xc = ax[k] - cmx, yc = ay[k] - cmy, zc = az[k] - cmz;
        e += fmaf(xc, xc, fmaf(yc, yc, zc * zc));
        if (k == q) {
            const int a = tid + 256 * k;
            f[3 * a + 0] = -0.25f * xc;
            f[3 * a + 1] = -0.25f * yc;
            f[3 * a + 2] = -0.25f * zc;
        }
    }
    e *= 0.125f;
    #pragma unroll
    for (int o = 16; o > 0; o >>= 1) e += __shfl_xor_sync(0xFFFFFFFFu, e, o);
    if (lane == 0) er[warp] = e;
    __syncthreads();
    if (q == 0 && tid == 0) {
        float es = 0.0f;
        #pragma unroll
        for (int k = 0; k < 8; k++) es += er[k];
        out[b] = es;
    }
}

// Minimal LJ core: a = 1/r^2; u = a^3 - 1; ae += u^2 (= e_term + 1, count fixed
// in epilogue); force coef c = a^4 * u = (r^-12 - r^-6)/r^2.  15 packed fma ops.
__device__ __forceinline__ void lj_core(
    ull xi2, ull yi2, ull zi2, ull nx2, ull ny2, ull nz2,
    int m, int m0, int m1, bool self_mask, ull MINUS1,
    ull& fx2, ull& fy2, ull& fz2, ull& ae)
{
    ull dx2 = f2add(xi2, nx2);
    ull dy2 = f2add(yi2, ny2);
    ull dz2 = f2add(zi2, nz2);
    ull sq2 = f2mul(dx2, dx2);
    sq2 = f2fma(dy2, dy2, sq2);
    sq2 = f2fma(dz2, dz2, sq2);
    float s0, s1;
    f2unpack(sq2, s0, s1);
    if (self_mask) {                    // self-pair -> rcp underflows to 0
        s0 = (m == m0) ? 3.0e38f : s0;
        s1 = (m == m1) ? 3.0e38f : s1;
    }
    float r0 = __fdividef(1.0f, s0);    // MUFU.RCP (self: denormal -> 0)
    float r1 = __fdividef(1.0f, s1);
    ull a  = f2pack(r0, r1);
    ull a2 = f2mul(a, a);
    ull a3 = f2mul(a2, a);
    ull a4 = f2mul(a2, a2);
    ull um = f2add(a3, MINUS1);         // r^-6 - 1  (self: -1)
    ae = f2fma(um, um, ae);             // += (r^-6 - 1)^2 = e_term + 1 (self: +1)
    ull c2 = f2mul(a4, um);             // a^7 - a^4 (self: 0)
    fx2 = f2fma(c2, dx2, fx2);
    fy2 = f2fma(c2, dy2, fy2);
    fz2 = f2fma(c2, dz2, fz2);
}

template <bool SELF>
__device__ __forceinline__ void quad_loop(
    const ulonglong2* __restrict__ SX, const ulonglong2* __restrict__ SY,
    const ulonglong2* __restrict__ SZ,
    ull xi2, ull yi2, ull zi2, int qa, int sub, int slot, ull MINUS1,
    ull& fx2, ull& fy2, ull& fz2, ull& ae)
{
    // core0 handles quad elems 0,1; core1 elems 2,3
    const int m0a = (SELF && sub == 0 && slot == 0) ? qa : -1;
    const int m1a = (SELF && sub == 0 && slot == 1) ? qa : -1;
    const int m0b = (SELF && sub == 1 && slot == 0) ? qa : -1;
    const int m1b = (SELF && sub == 1 && slot == 1) ? qa : -1;
    #pragma unroll 4
    for (int t = 0; t < NQUADS; t++) {
        ulonglong2 X = SX[t], Y = SY[t], Z = SZ[t];   // broadcast LDS.128 x3
        lj_core(xi2, yi2, zi2, X.x, Y.x, Z.x, t, m0a, m1a, SELF, MINUS1,
                fx2, fy2, fz2, ae);
        lj_core(xi2, yi2, zi2, X.y, Y.y, Z.y, t, m0b, m1b, SELF, MINUS1,
                fx2, fy2, fz2, ae);
    }
}

__global__ __launch_bounds__(TPB, 4) void lj_kernel(const float* __restrict__ pos,
                                                    float* __restrict__ out) {
    __shared__ ulonglong2 sxq[NQUADS];   // {x01, x23} negated
    __shared__ ulonglong2 syq[NQUADS];
    __shared__ ulonglong2 szq[NQUADS];
    __shared__ float      ered[8];

    const int bi    = blockIdx.x;
    const int b     = bi >> 4;
    const int chunk = (bi >> 2) & 3;     // i-chunk (256 atoms)
    const int jp    = bi & 3;            // j-quarter (256 atoms)
    const int tid   = threadIdx.x;
    const int lane  = tid & 31;
    const int warp  = tid >> 5;

    const float* __restrict__ p = pos + (size_t)b * NATOMS * 3;

    // stage j-quarter as 64 quads (threads 0..63; 3 aligned float4 loads each)
    if (tid < NQUADS) {
        const float4* pj = (const float4*)(p + 3 * (jp * JTILE + 4 * tid));
        float4 A = pj[0];                // x0 y0 z0 x1
        float4 B = pj[1];                // y1 z1 x2 y2
        float4 C = pj[2];                // z2 x3 y3 z3
        ulonglong2 X, Y, Z;
        X.x = f2pack(-A.x, -A.w); X.y = f2pack(-B.z, -C.y);
        Y.x = f2pack(-A.y, -B.x); Y.y = f2pack(-B.w, -C.z);
        Z.x = f2pack(-A.z, -B.y); Z.y = f2pack(-C.x, -C.w);
        sxq[tid] = X; syq[tid] = Y; szq[tid] = Z;
    }

    // own i-atom
    const int i = chunk * TPB + tid;
    const float xi = p[3 * i + 0];
    const float yi = p[3 * i + 1];
    const float zi = p[3 * i + 2];
    __syncthreads();

    const ull xi2 = f2pack(xi, xi);
    const ull yi2 = f2pack(yi, yi);
    const ull zi2 = f2pack(zi, zi);
    const ull MINUS1 = f2pack(-1.0f, -1.0f);

    ull fx2 = 0, fy2 = 0, fz2 = 0, ae = 0;

    if (chunk == jp) {
        const int qa   = tid >> 2;           // self quad
        const int sub  = (tid >> 1) & 1;     // which core
        const int slot = tid & 1;            // which packed lane
        quad_loop<true>(sxq, syq, szq, xi2, yi2, zi2, qa, sub, slot, MINUS1,
                        fx2, fy2, fz2, ae);
    } else {
        quad_loop<false>(sxq, syq, szq, xi2, yi2, zi2, 0, 0, 0, MINUS1,
                         fx2, fy2, fz2, ae);
    }

    // energy: Sum u^2 over 256 j = Sum(e_term) + 256 -> subtract count, halve
    float ael, aeh;
    f2unpack(ae, ael, aeh);
    float e = 0.5f * ((ael + aeh) - 256.0f);

    // forces: out preloaded with oscillator force by lj_pre; 4 partials per atom
    float lo, hi;
    float* __restrict__ f = out + NBATCH + (size_t)(b * NATOMS + i) * 3;
    f2unpack(fx2, lo, hi); atomicAdd(f + 0, 12.0f * (lo + hi));
    f2unpack(fy2, lo, hi); atomicAdd(f + 1, 12.0f * (lo + hi));
    f2unpack(fz2, lo, hi); atomicAdd(f + 2, 12.0f * (lo + hi));

    // energy: warp shuffles -> shared -> one atomicAdd per block
    #pragma unroll
    for (int o = 16; o > 0; o >>= 1)
        e += __shfl_xor_sync(0xFFFFFFFFu, e, o);
    if (lane == 0) ered[warp] = e;
    __syncthreads();
    if (tid == 0) {
        float es = 0.0f;
        #pragma unroll
        for (int k = 0; k < 8; k++) es += ered[k];
        atomicAdd(out + b, es);
    }
}

extern "C" void kernel_launch(void* const* d_in, const int* in_sizes, int n_in,
                              void* d_out, int out_size) {
    const float* pos = (const float*)d_in[0];
    float* out = (float*)d_out;
    lj_pre<<<4 * NBATCH, 256>>>(pos, out);
    lj_kernel<<<NBATCH * 4 * JQ, TPB>>>(pos, out);
}